// round 1
// baseline (speedup 1.0000x reference)
#include <cuda_runtime.h>
#include <math.h>

#define N_NODE 200
#define N_HID  1500
#define N_BAT  20
#define N_IN   6

// ---------------- scratch (static device globals; no allocation) ----------------
__device__ float g_wl[N_NODE * N_NODE];
__device__ float g_rowsum[N_NODE];
__device__ float g_part[N_NODE];
__device__ float g_invnorm;
__device__ float g_ls[N_NODE * N_NODE];

// ---------------- prep: build l_s = w_n - diag(rowsum(w_n)) ----------------
__global__ void prep1_kernel(const float* __restrict__ sc, const float* __restrict__ wbb) {
    int r = blockIdx.x;
    int c = threadIdx.x;
    float wl = 0.f;
    if (c < N_NODE) {
        float w_rc = expf(wbb[r * N_NODE + c]) * sc[r * N_NODE + c];
        float w_cr = expf(wbb[c * N_NODE + r]) * sc[c * N_NODE + r];
        wl = log1pf(0.5f * (w_rc + w_cr));
        g_wl[r * N_NODE + c] = wl;
    }
    __shared__ float s1[256], s2[256];
    s1[threadIdx.x] = wl;
    s2[threadIdx.x] = wl * wl;
    __syncthreads();
    for (int s = 128; s > 0; s >>= 1) {
        if (threadIdx.x < s) {
            s1[threadIdx.x] += s1[threadIdx.x + s];
            s2[threadIdx.x] += s2[threadIdx.x + s];
        }
        __syncthreads();
    }
    if (threadIdx.x == 0) {
        g_rowsum[r] = s1[0];  // row sum of w_l (deterministic)
        g_part[r]   = s2[0];  // partial sum of squares (deterministic)
    }
}

__global__ void prep2_kernel() {
    __shared__ float s[256];
    int t = threadIdx.x;
    s[t] = (t < N_NODE) ? g_part[t] : 0.f;
    __syncthreads();
    for (int k = 128; k > 0; k >>= 1) {
        if (t < k) s[t] += s[t + k];
        __syncthreads();
    }
    if (t == 0) g_invnorm = 1.f / sqrtf(s[0]);
}

__global__ void prep3_kernel() {
    int r = blockIdx.x;
    int c = threadIdx.x;
    if (c < N_NODE) {
        float v = g_wl[r * N_NODE + c];
        if (c == r) v -= g_rowsum[r];
        g_ls[r * N_NODE + c] = v * g_invnorm;
    }
}

// ---------------- simulation ----------------
__device__ __forceinline__ float h_tf_dev(float a, float b, float d, float z) {
    float u = a * z - b;
    float num = 1e-5f + fabsf(u);
    float den = 1e-5f * d + fabsf(1.0f - __expf(-d * u));
    return num / den;
}

__device__ __forceinline__ float tanh_pos(float y) {
    // y >= 1e-5; tanh(y) = (1 - e^{-2y}) / (1 + e^{-2y})
    float t = __expf(-2.f * y);
    return (1.f - t) / (1.f + t);
}

__global__ void __launch_bounds__(800, 1) sim_kernel(
    const float* __restrict__ ext,   // (200,1500,20,6)
    const float* __restrict__ hx,    // (200,6)
    float* __restrict__ out,         // (200,20)
    const float* gp, const float* gEEp, const float* gIEp,
    const float* gEIp, const float* stdp)
{
    __shared__ float Ebuf[2][N_NODE];

    const int tid = threadIdx.x;
    const int w   = tid >> 5;
    const int l   = tid & 31;
    const int row = w * 8 + (l & 7);     // 0..199
    const int cb  = (l >> 3) * 50;       // 0,50,100,150

    // Load this lane's W slice into registers (amortized over 30000 steps)
    float W[50];
#pragma unroll
    for (int k = 0; k < 50; k++) W[k] = g_ls[row * N_NODE + cb + k];

    const float gg   = *gp;
    const float cEE  = 0.001f + fmaxf(*gEEp, 0.f);
    const float cIE  = 0.001f + fmaxf(*gIEp, 0.f);
    const float cEI  = 0.001f + fmaxf(*gEIp, 0.f);
    const float s_in = 0.02f + fmaxf(*stdp, 0.f);
    const float dt   = 0.5f;
    const float sqdt = 0.70710678118654752440f;       // sqrt(0.5) in f32
    const float ln066 = -0.41551544396166582194f;     // log(0.66)

    float E = 0.f, I = 0.f, X = 0.f, F = 0.f, V = 0.f, Q = 0.f;
    const bool owner = (l < 8);
    if (owner) {
        E = hx[row * 6 + 0];
        I = hx[row * 6 + 1];
        X = hx[row * 6 + 2];
        F = hx[row * 6 + 3];
        V = hx[row * 6 + 4];
        Q = hx[row * 6 + 5];
        Ebuf[0][row] = E;
    }
    __syncthreads();

    int p = 0;
#pragma unroll 1
    for (int b = 0; b < N_BAT; b++) {
#pragma unroll 1
        for (int h = 0; h < N_HID; h++) {
            // noise for this (row, h, b): issue early, consumed ~700cyc later
            const float2 nn = *(const float2*)(ext + ((size_t)(row * N_HID + h) * N_BAT + b) * N_IN);

            // matvec partial: row dot E over this lane's 50 columns
            float acc0 = 0.f, acc1 = 0.f;
            const float* Eb = &Ebuf[p][cb];
#pragma unroll
            for (int k = 0; k < 50; k += 2) {
                float2 e = *(const float2*)(Eb + k);
                acc0 = fmaf(W[k],     e.x, acc0);
                acc1 = fmaf(W[k + 1], e.y, acc1);
            }
            float acc = acc0 + acc1;
            acc += __shfl_xor_sync(0xffffffffu, acc, 8);
            acc += __shfl_xor_sync(0xffffffffu, acc, 16);

            if (owner) {
                float IE = fmaxf(0.32f + cEE * E + gg * acc - cIE * I, 0.f);
                float II = fmaxf(0.224f + cEI * E - I, 0.f);
                float rE = h_tf_dev(310.f, 125.f, 0.16f,  IE);
                float rI = h_tf_dev(615.f, 177.f, 0.087f, II);
                float En = E + dt * (-E / 100.f + 0.000641f * (1.f - E) * rE) + sqdt * nn.x * s_in;
                float In = I + dt * (-I / 10.f  + 0.001f * rI)                + sqdt * nn.y * s_in;
                E = tanh_pos(1e-5f + fmaxf(En, 0.f));
                I = tanh_pos(1e-5f + fmaxf(In, 0.f));
                Ebuf[p ^ 1][row] = E;

                // hemodynamics (off the E/I critical chain, overlaps next matvec issue)
                X = X + dt * (E - X / 0.65f - (F - 1.f) / 0.41f);
                F = F + dt * X;
                float vp = __expf(3.125f * __logf(V));
                float Vn = V + dt * (F - vp) / 0.98f;
                float vq = __expf(3.125f * __logf(Vn));
                Q = Q + dt * (F * (1.f - __expf(ln066 / F)) / 0.34f - Q * vq / Vn) / 0.98f;
                V = Vn;
            }
            __syncthreads();
            p ^= 1;
        }
        if (owner) {
            float n2 = ext[((size_t)(row * N_HID + (N_HID - 1)) * N_BAT + b) * N_IN + 2];
            float bold = 0.02f * n2 +
                         5.8823529411764705882f * (2.38f * (1.f - Q) + 2.f * (1.f - Q / V) + 0.48f * (1.f - V));
            out[row * N_BAT + b] = bold;
        }
    }
}

// ---------------- launch ----------------
extern "C" void kernel_launch(void* const* d_in, const int* in_sizes, int n_in,
                              void* d_out, int out_size) {
    const float* ext  = (const float*)d_in[0];  // external (200,1500,20,6)
    const float* hx   = (const float*)d_in[1];  // hx (200,6)
    // d_in[2] = hE (unused by reference)
    const float* sc   = (const float*)d_in[3];  // sc (200,200)
    const float* wbb  = (const float*)d_in[4];  // w_bb (200,200)
    const float* gp   = (const float*)d_in[5];
    const float* gEE  = (const float*)d_in[6];
    const float* gIE  = (const float*)d_in[7];
    const float* gEI  = (const float*)d_in[8];
    const float* stdp = (const float*)d_in[9];
    float* out = (float*)d_out;

    prep1_kernel<<<N_NODE, 256>>>(sc, wbb);
    prep2_kernel<<<1, 256>>>();
    prep3_kernel<<<N_NODE, 256>>>();
    sim_kernel<<<1, 800>>>(ext, hx, out, gp, gEE, gIE, gEI, stdp);
}

// round 2
// speedup vs baseline: 1.6983x; 1.6983x over previous
#include <cuda_runtime.h>
#include <math.h>

#define N_NODE 200
#define N_HID  1500
#define N_BAT  20
#define N_IN   6
#define PADC   52          // padded column-block width (16B-aligned float4 blocks)

// ---------------- scratch (static device globals; no allocation) ----------------
__device__ float g_wl[N_NODE * N_NODE];
__device__ float g_rowsum[N_NODE];
__device__ float g_part[N_NODE];
__device__ float g_invnorm;
__device__ float g_ls[N_NODE * N_NODE];

// ---------------- prep: build l_s = w_n - diag(rowsum(w_n)) ----------------
__global__ void prep1_kernel(const float* __restrict__ sc, const float* __restrict__ wbb) {
    int r = blockIdx.x;
    int c = threadIdx.x;
    float wl = 0.f;
    if (c < N_NODE) {
        float w_rc = expf(wbb[r * N_NODE + c]) * sc[r * N_NODE + c];
        float w_cr = expf(wbb[c * N_NODE + r]) * sc[c * N_NODE + r];
        wl = log1pf(0.5f * (w_rc + w_cr));
        g_wl[r * N_NODE + c] = wl;
    }
    __shared__ float s1[256], s2[256];
    s1[threadIdx.x] = wl;
    s2[threadIdx.x] = wl * wl;
    __syncthreads();
    for (int s = 128; s > 0; s >>= 1) {
        if (threadIdx.x < s) {
            s1[threadIdx.x] += s1[threadIdx.x + s];
            s2[threadIdx.x] += s2[threadIdx.x + s];
        }
        __syncthreads();
    }
    if (threadIdx.x == 0) {
        g_rowsum[r] = s1[0];
        g_part[r]   = s2[0];
    }
}

__global__ void prep2_kernel() {
    __shared__ float s[256];
    int t = threadIdx.x;
    s[t] = (t < N_NODE) ? g_part[t] : 0.f;
    __syncthreads();
    for (int k = 128; k > 0; k >>= 1) {
        if (t < k) s[t] += s[t + k];
        __syncthreads();
    }
    if (t == 0) g_invnorm = 1.f / sqrtf(s[0]);
}

__global__ void prep3_kernel() {
    int r = blockIdx.x;
    int c = threadIdx.x;
    if (c < N_NODE) {
        float v = g_wl[r * N_NODE + c];
        if (c == r) v -= g_rowsum[r];
        g_ls[r * N_NODE + c] = v * g_invnorm;
    }
}

// ---------------- simulation helpers ----------------
__device__ __forceinline__ float h_tf_dev(float a, float b, float d, float z) {
    float u   = fmaf(a, z, -b);
    float num = 1e-5f + fabsf(u);
    float den = fmaf(1e-5f, d, fabsf(1.0f - __expf(-d * u)));
    return __fdividef(num, den);
}

__device__ __forceinline__ float tanh_pos(float y) {
    // y >= 1e-5; tanh(y) = (1 - e^{-2y}) / (1 + e^{-2y})
    float t = __expf(-2.f * y);
    return __fdividef(1.f - t, 1.f + t);
}

#define FMA2(acc, a, b) \
    asm("fma.rn.f32x2 %0, %1, %2, %0;" : "+l"(acc) : "l"(a), "l"(b))

__global__ void __launch_bounds__(800, 1) sim_kernel(
    const float* __restrict__ ext,   // (200,1500,20,6)
    const float* __restrict__ hx,    // (200,6)
    float* __restrict__ out,         // (200,20)
    const float* gp, const float* gEEp, const float* gIEp,
    const float* gEIp, const float* stdp)
{
    __shared__ __align__(16) float Ebuf[2][4 * PADC];   // 2 x 208
    __shared__ float Acc[N_NODE];

    const int tid = threadIdx.x;
    const int w   = tid >> 5;
    const int l   = tid & 31;
    const int row = w * 8 + (l & 7);        // 0..199
    const int cbl = (l >> 3) * 50;          // logical col start
    const int pcb = (l >> 3) * PADC;        // physical col start (16B aligned)

    // ---- load W slice into registers as 26 packed f32x2 pairs (pad -> 0) ----
    unsigned long long W2[PADC / 2];
#pragma unroll
    for (int j = 0; j < PADC / 2; j++) {
        int k0 = 2 * j, k1 = 2 * j + 1;
        float w0 = (k0 < 50) ? g_ls[row * N_NODE + cbl + k0] : 0.f;
        float w1 = (k1 < 50) ? g_ls[row * N_NODE + cbl + k1] : 0.f;
        asm("mov.b64 %0, {%1, %2};" : "=l"(W2[j]) : "f"(w0), "f"(w1));
    }

    const float gg   = *gp;
    const float cEE  = 0.001f + fmaxf(*gEEp, 0.f);
    const float cIE  = 0.001f + fmaxf(*gIEp, 0.f);
    const float cEI  = 0.001f + fmaxf(*gEIp, 0.f);
    const float s_in = 0.02f + fmaxf(*stdp, 0.f);
    const float sqdt = 0.70710678118654752440f;
    const float ln066 = -0.41551544396166582194f;   // log(0.66)
    const float it0  = 0.5f / 0.98f;                // dt / tau_0
    const float its  = 1.f / 0.65f;
    const float itf  = 1.f / 0.41f;
    const float irho = 1.f / 0.34f;

    // ---- per-node state lives only in threads tid < 200 ----
    float E = 0.f, I = 0.f, X = 0.f, F = 0.f, V = 0.f, Q = 0.f, vpow = 0.f;
    const bool tail = (tid < N_NODE);
    const int epos  = (tid / 50) * PADC + (tid % 50);   // padded write slot

    // zero both E buffers (pads must be exactly 0)
    for (int i = tid; i < 2 * 4 * PADC; i += 800)
        ((float*)Ebuf)[i] = 0.f;
    __syncthreads();

    if (tail) {
        E = hx[tid * 6 + 0];
        I = hx[tid * 6 + 1];
        X = hx[tid * 6 + 2];
        F = hx[tid * 6 + 3];
        V = hx[tid * 6 + 4];
        Q = hx[tid * 6 + 5];
        vpow = __expf(3.125f * __logf(V));   // V^(1/alpha)
        Ebuf[0][epos] = E;
    }
    __syncthreads();

    const float* noisebase = ext + (size_t)tid * (N_HID * N_BAT * N_IN);

    float* curE = Ebuf[0];
    float* nxtE = Ebuf[1];

#define HEMO_STEP                                                              \
    do {                                                                       \
        X = X + 0.5f * (E - X * its - (F - 1.f) * itf);                        \
        F = F + 0.5f * X;                                                      \
        float Vn = fmaf(it0, F - vpow, V);                                     \
        float vq = __expf(3.125f * __logf(Vn));                                \
        float qa = F * (1.f - __expf(__fdividef(ln066, F))) * irho;            \
        float qb = __fdividef(Q * vq, Vn);                                     \
        Q = fmaf(it0, qa - qb, Q);                                             \
        V = Vn; vpow = vq;                                                     \
    } while (0)

#pragma unroll 1
    for (int b = 0; b < N_BAT; b++) {
        const float* np = noisebase + b * N_IN;
#pragma unroll 1
        for (int h = 0; h < N_HID; h++) {
            float nx = 0.f, ny = 0.f;
            if (tail) {
                float2 nn = *(const float2*)np;     // issued early, used late
                nx = nn.x; ny = nn.y;
                np += N_BAT * N_IN;
                if (h > 0) HEMO_STEP;               // deferred hemo overlaps matvec
            }

            // ---- matvec partial: 13 x LDS.128 + 26 x FFMA2 ----
            unsigned long long a0 = 0ull, a1 = 0ull;
            const ulonglong2* Eb = reinterpret_cast<const ulonglong2*>(curE + pcb);
#pragma unroll
            for (int k = 0; k < PADC / 4; k++) {
                ulonglong2 e = Eb[k];
                FMA2(a0, W2[2 * k],     e.x);
                FMA2(a1, W2[2 * k + 1], e.y);
            }
            float l0, h0, l1, h1;
            asm("mov.b64 {%0, %1}, %2;" : "=f"(l0), "=f"(h0) : "l"(a0));
            asm("mov.b64 {%0, %1}, %2;" : "=f"(l1), "=f"(h1) : "l"(a1));
            float s = (l0 + h0) + (l1 + h1);
            s += __shfl_xor_sync(0xffffffffu, s, 8);
            s += __shfl_xor_sync(0xffffffffu, s, 16);
            if (l < 8) Acc[row] = s;
            __syncthreads();                        // Acc ready

            if (tail) {
                float acc = gg * Acc[tid];
                float IE = fmaxf(acc + fmaf(cEE, E, 0.32f) - cIE * I, 0.f);
                float II = fmaxf(fmaf(cEI, E, 0.224f) - I, 0.f);
                float rE = h_tf_dev(310.f, 125.f, 0.16f,  IE);
                float rI = h_tf_dev(615.f, 177.f, 0.087f, II);
                float En = E + 0.5f * fmaf(0.000641f * (1.f - E), rE, -0.01f * E)
                             + (sqdt * s_in) * nx;
                float In = I + 0.5f * fmaf(0.001f, rI, -0.1f * I)
                             + (sqdt * s_in) * ny;
                E = tanh_pos(1e-5f + fmaxf(En, 0.f));
                I = tanh_pos(1e-5f + fmaxf(In, 0.f));
                nxtE[epos] = E;
            }
            __syncthreads();                        // E(next) ready
            float* t2 = curE; curE = nxtE; nxtE = t2;
        }
        if (tail) {
            HEMO_STEP;                              // hemo for h = 1499
            float n2 = noisebase[b * N_IN + (N_HID - 1) * N_BAT * N_IN + 2];
            float bold = 0.02f * n2 +
                5.8823529411764705882f * (2.38f * (1.f - Q)
                                        + 2.f * (1.f - __fdividef(Q, V))
                                        + 0.48f * (1.f - V));
            out[tid * N_BAT + b] = bold;
        }
    }
}

// ---------------- launch ----------------
extern "C" void kernel_launch(void* const* d_in, const int* in_sizes, int n_in,
                              void* d_out, int out_size) {
    const float* ext  = (const float*)d_in[0];  // external (200,1500,20,6)
    const float* hx   = (const float*)d_in[1];  // hx (200,6)
    // d_in[2] = hE (unused by reference)
    const float* sc   = (const float*)d_in[3];  // sc (200,200)
    const float* wbb  = (const float*)d_in[4];  // w_bb (200,200)
    const float* gp   = (const float*)d_in[5];
    const float* gEE  = (const float*)d_in[6];
    const float* gIE  = (const float*)d_in[7];
    const float* gEI  = (const float*)d_in[8];
    const float* stdp = (const float*)d_in[9];
    float* out = (float*)d_out;

    prep1_kernel<<<N_NODE, 256>>>(sc, wbb);
    prep2_kernel<<<1, 256>>>();
    prep3_kernel<<<N_NODE, 256>>>();
    sim_kernel<<<1, 800>>>(ext, hx, out, gp, gEE, gIE, gEI, stdp);
}